// round 15
// baseline (speedup 1.0000x reference)
#include <cuda_runtime.h>
#include <math.h>

#define B 128
#define L 1024
#define CTAS 1024             // 8 CTAs per batch, 128 rows per CTA
#define GROUPS 16             // 16 rows per warp (8 warps x 16 = 128 rows per CTA)
#define NSTAGE (GROUPS * 4)   // 64 quarter-row stages per warp
#define P_TX 10.0f
#define P_NOISE 6.2946e-14f

typedef unsigned int u32;

__device__ float g_bsum[CTAS];            // per-CTA partial sums of R
__device__ float g_inv[B];                // per-batch 1/sum
__device__ unsigned int g_cnt[B] = {};    // per-batch completion counters (to 8)
__device__ unsigned int g_final = 0;      // final completion counter (to 128)

__device__ __forceinline__ float warp_sum(float v) {
    #pragma unroll
    for (int o = 16; o; o >>= 1) v += __shfl_xor_sync(0xffffffffu, v, o);
    return v;
}

__device__ __forceinline__ unsigned int atom_add_acqrel(unsigned int* p) {
    unsigned int old;
    asm volatile("atom.add.acq_rel.gpu.u32 %0, [%1], 1;"
                 : "=r"(old) : "l"(p) : "memory");
    return old;
}

// Issue one quarter-row stage (1 KB) via cp.async.cg; always commit (empty
// groups at the tail keep wait_group counting consistent).
__device__ __forceinline__ void issue_stage(int q, u32 warpbuf,
                                            const float* HwBase, int lane) {
    if (q < NSTAGE) {
        u32 dst = warpbuf + (q & 1) * 1024 + lane * 16;
        const float* src = HwBase + (size_t)(q >> 2) * (8 * L) + (q & 3) * 256 + lane * 4;
        asm volatile("cp.async.cg.shared.global [%0], [%1], 16;" :: "r"(dst), "l"(src));
        asm volatile("cp.async.cg.shared.global [%0], [%1], 16;" :: "r"(dst + 512), "l"(src + 128));
    }
    asm volatile("cp.async.commit_group;" ::: "memory");
}

// Persistent-style: each CTA owns 128 consecutive rows of one batch.
// H streamed via cp.async double-buffered smem stages (loads never drain at
// group boundaries); staged Py; fence-free hierarchical finalize.
__global__ void __launch_bounds__(256, 8) fused_kernel(const float* __restrict__ H,
                                                       const float* __restrict__ prob,
                                                       float* __restrict__ out) {
    const int wid   = threadIdx.x >> 5;
    const int lane  = threadIdx.x & 31;
    const int b     = blockIdx.x >> 3;                  // 8 CTAs per batch
    const int rbase = blockIdx.x * 128;                 // first global row of this CTA

    __shared__ float sPy[L];                            // P * y[b, :]
    __shared__ __align__(16) float sBuf[8][512];        // per-warp 2-slot ring (2 KB)
    __shared__ float sR[8];

    {
        const float4* __restrict__ p4 =
            reinterpret_cast<const float4*>(prob + 2 * (size_t)b * L);
        #pragma unroll
        for (int i = 0; i < 2; i++) {
            int j = i * 256 + threadIdx.x;              // float4 index in [0, 512)
            float4 v = __ldg(p4 + j);
            sPy[2 * j]     = P_TX * v.y;
            sPy[2 * j + 1] = P_TX * v.w;
        }
    }
    __syncthreads();

    const float4* __restrict__ s4 = reinterpret_cast<const float4*>(sPy);
    const float*  HwBase = H + (size_t)(rbase + wid) * L;   // warp's first row
    const int     kbase  = ((blockIdx.x & 7) * 128) + wid;  // its diagonal column
    const u32 warpbuf = (u32)__cvta_generic_to_shared(&sBuf[wid][0]);

    // Prologue: 2 stages in flight.
    issue_stage(0, warpbuf, HwBase, lane);
    issue_stage(1, warpbuf, HwBase, lane);

    float rsum = 0.0f;                  // per-warp R accumulator (identical all lanes)

    #pragma unroll 1
    for (int g = 0; g < GROUPS; g++) {
        // Diagonal: issued early, consumed after quarter 3 (latency hidden).
        float dval = __ldg(HwBase + (size_t)g * (8 * L) + kbase + g * 8);

        float acc = 0.0f;
        #pragma unroll
        for (int quarter = 0; quarter < 4; quarter++) {
            const int q = g * 4 + quarter;
            asm volatile("cp.async.wait_group 1;" ::: "memory");  // stage q ready

            const float4* hs =
                reinterpret_cast<const float4*>(&sBuf[wid][(q & 1) * 256]);
            float4 h0 = hs[lane];            // own-lane data only (no cross-lane)
            float4 h1 = hs[32 + lane];
            float4 p0 = s4[quarter * 64 + lane];
            float4 p1 = s4[quarter * 64 + 32 + lane];

            acc = fmaf(h0.x * h0.x, p0.x, acc);
            acc = fmaf(h0.y * h0.y, p0.y, acc);
            acc = fmaf(h0.z * h0.z, p0.z, acc);
            acc = fmaf(h0.w * h0.w, p0.w, acc);
            acc = fmaf(h1.x * h1.x, p1.x, acc);
            acc = fmaf(h1.y * h1.y, p1.y, acc);
            acc = fmaf(h1.z * h1.z, p1.z, acc);
            acc = fmaf(h1.w * h1.w, p1.w, acc);

            // Slot (q&1) consumed above -> safe to refill with stage q+2.
            // Copy engine streams it while the epilogue below runs.
            issue_stage(q + 2, warpbuf, HwBase, lane);
        }

        acc = warp_sum(acc);

        const int k = kbase + g * 8;
        float sig = dval * dval * sPy[k];
        rsum += log1pf(__fdividef(sig, (acc - sig) + P_NOISE)) * 1.4426950408889634f;
    }

    if (lane == 0) sR[wid] = rsum;
    __syncthreads();

    if (wid != 0) return;

    // Warp 0: combine 8 warp sums, publish partial, run completion protocol.
    float s = (lane < 8) ? sR[lane] : 0.0f;
    s = warp_sum(s);

    bool last_in_batch = false;
    if (lane == 0) {
        __stcg(&g_bsum[blockIdx.x], s);                 // L2 = coherence point
        unsigned int t = atom_add_acqrel(&g_cnt[b]);    // release orders the stcg
        last_in_batch = (t == 7u);
    }
    last_in_batch = __shfl_sync(0xffffffffu, last_in_batch, 0);
    if (!last_in_batch) return;

    // ---- Per-batch tail: reduce this batch's 8 partials ----
    {
        float v = (lane < 8) ? __ldcg(g_bsum + b * 8 + lane) : 0.0f;
        v = warp_sum(v);

        bool last_final = false;
        if (lane == 0) {
            __stcg(&g_inv[b], 1.0f / v);
            g_cnt[b] = 0;                               // reset for next replay
            unsigned int u = atom_add_acqrel(&g_final); // release orders the stcg
            last_final = (u == (unsigned int)(B - 1));
        }
        last_final = __shfl_sync(0xffffffffu, last_final, 0);
        if (!last_final) return;
    }

    // ---- Global tail: one warp reduces 128 per-batch inverses ----
    {
        const float4* __restrict__ p = reinterpret_cast<const float4*>(g_inv);
        float4 v = __ldcg(p + lane);                    // 128 values
        float sv = (v.x + v.y) + (v.z + v.w);
        sv = warp_sum(sv);
        if (lane == 0) {
            out[0] = sv * (1.0f / (float)B);
            g_final = 0;                                // reset for next replay
        }
    }
}

extern "C" void kernel_launch(void* const* d_in, const int* in_sizes, int n_in,
                              void* d_out, int out_size) {
    const float* prob = (const float*)d_in[0];
    const float* H    = (const float*)d_in[1];
    if (in_sizes[0] != 2 * B * L) { prob = (const float*)d_in[1]; H = (const float*)d_in[0]; }

    fused_kernel<<<CTAS, 256>>>(H, prob, (float*)d_out);
}

// round 16
// speedup vs baseline: 1.0927x; 1.0927x over previous
#include <cuda_runtime.h>
#include <math.h>

#define B 128
#define L 1024
#define CTAS 1024             // 8 CTAs per batch, 128 rows per CTA
#define GROUPS 16             // 16 groups x 8 rows = 128 rows per CTA
#define P_TX 10.0f
#define P_NOISE 6.2946e-14f

__device__ float g_bsum[CTAS];            // per-CTA partial sums of R
__device__ float g_inv[B];                // per-batch 1/sum
__device__ unsigned int g_cnt[B] = {};    // per-batch completion counters (to 8)
__device__ unsigned int g_final = 0;      // final completion counter (to 128)

__inline__ __device__ float warp_reduce(float v) {
    #pragma unroll
    for (int o = 16; o; o >>= 1) v += __shfl_down_sync(0xffffffffu, v, o);
    return v;
}

__device__ __forceinline__ unsigned int atom_add_acqrel(unsigned int* p) {
    unsigned int old;
    asm volatile("atom.add.acq_rel.gpu.u32 %0, [%1], 1;"
                 : "=r"(old) : "l"(p) : "memory");
    return old;
}

// Persistent-style: each CTA owns 128 consecutive rows of one batch.
// Stage Py once, then 16 row-groups (warp-per-row), then fence-free finalize.
__global__ void __launch_bounds__(256) fused_kernel(const float* __restrict__ H,
                                                    const float* __restrict__ prob,
                                                    float* __restrict__ out) {
    const int wid   = threadIdx.x >> 5;
    const int lane  = threadIdx.x & 31;
    const int b     = blockIdx.x >> 3;                  // 8 CTAs per batch
    const int rbase = blockIdx.x * 128;                 // first global row of this CTA

    __shared__ float sPy[L];            // P * y[b, :]  (4 KB), staged ONCE
    __shared__ float sR[8];

    {
        const float4* __restrict__ p4 =
            reinterpret_cast<const float4*>(prob + 2 * (size_t)b * L);
        #pragma unroll
        for (int i = 0; i < 2; i++) {
            int j = i * 256 + threadIdx.x;              // float4 index in [0, 512)
            float4 v = __ldg(p4 + j);
            sPy[2 * j]     = P_TX * v.y;
            sPy[2 * j + 1] = P_TX * v.w;
        }
    }
    __syncthreads();

    const float4* __restrict__ s4 = reinterpret_cast<const float4*>(sPy);

    float rsum = 0.0f;                  // lane 0 of each warp accumulates R over groups

    #pragma unroll 1
    for (int g = 0; g < GROUPS; g++) {
        const int row = rbase + g * 8 + wid;            // global row
        const int k   = row & (L - 1);
        const float4* __restrict__ h4 =
            reinterpret_cast<const float4*>(H + (size_t)row * L);

        float acc = 0.0f;
        #pragma unroll
        for (int i = 0; i < 8; i++) {
            const int t = i * 32 + lane;
            float4 h = __ldcs(h4 + t);  // evict-first: H read exactly once
            float4 p = s4[t];           // conflict-free LDS.128
            acc = fmaf(h.x * h.x, p.x, acc);
            acc = fmaf(h.y * h.y, p.y, acc);
            acc = fmaf(h.z * h.z, p.z, acc);
            acc = fmaf(h.w * h.w, p.w, acc);
        }
        acc = warp_reduce(acc);

        if (lane == 0) {
            float d      = __ldg(H + (size_t)row * L + k);   // diagonal (L2 hit)
            float signal = d * d * sPy[k];
            float interf = acc - signal;
            rsum += log1pf(__fdividef(signal, interf + P_NOISE)) * 1.4426950408889634f;
        }
    }

    if (lane == 0) sR[wid] = rsum;
    __syncthreads();

    if (wid != 0) return;

    // Warp 0: combine 8 warp sums, publish partial, run completion protocol.
    float s = (lane < 8) ? sR[lane] : 0.0f;
    s = warp_reduce(s);
    s = __shfl_sync(0xffffffffu, s, 0);

    bool last_in_batch = false;
    if (lane == 0) {
        __stcg(&g_bsum[blockIdx.x], s);                 // L2 = coherence point
        unsigned int t = atom_add_acqrel(&g_cnt[b]);    // release orders the stcg
        last_in_batch = (t == 7u);
    }
    last_in_batch = __shfl_sync(0xffffffffu, last_in_batch, 0);
    if (!last_in_batch) return;

    // ---- Per-batch tail: reduce this batch's 8 partials ----
    {
        float v = (lane < 8) ? __ldcg(g_bsum + b * 8 + lane) : 0.0f;
        v = warp_reduce(v);

        bool last_final = false;
        if (lane == 0) {
            __stcg(&g_inv[b], 1.0f / v);
            g_cnt[b] = 0;                               // reset for next replay
            unsigned int u = atom_add_acqrel(&g_final); // release orders the stcg
            last_final = (u == (unsigned int)(B - 1));
        }
        last_final = __shfl_sync(0xffffffffu, last_final, 0);
        if (!last_final) return;
    }

    // ---- Global tail: one warp reduces 128 per-batch inverses ----
    {
        const float4* __restrict__ p = reinterpret_cast<const float4*>(g_inv);
        float4 v = __ldcg(p + lane);                    // 128 values
        float sv = (v.x + v.y) + (v.z + v.w);
        sv = warp_reduce(sv);
        if (lane == 0) {
            out[0] = sv * (1.0f / (float)B);
            g_final = 0;                                // reset for next replay
        }
    }
}

extern "C" void kernel_launch(void* const* d_in, const int* in_sizes, int n_in,
                              void* d_out, int out_size) {
    const float* prob = (const float*)d_in[0];
    const float* H    = (const float*)d_in[1];
    if (in_sizes[0] != 2 * B * L) { prob = (const float*)d_in[1]; H = (const float*)d_in[0]; }

    fused_kernel<<<CTAS, 256>>>(H, prob, (float*)d_out);
}